// round 2
// baseline (speedup 1.0000x reference)
#include <cuda_runtime.h>

// NavierStokesLossMAC: fused residual + masked MSE over interior, per batch.
// Register-rolling stencil: each block processes an 8-row full-width strip,
// loading every global row exactly once.

static constexpr int B = 8;
static constexpr int H = 1024;
static constexpr int W = 1024;
static constexpr float MU = 0.1f;
static constexpr float INV_DT = 0.25f;   // 1/DT, DT=4
static constexpr int ROWS = 8;           // strip height per block

__device__ double g_accum[B];

__global__ void ns_zero_kernel() {
    if (threadIdx.x < B) g_accum[threadIdx.x] = 0.0;
}

// Load one row of a velocity channel: time-average, x-halos (clamped), dt term.
__device__ __forceinline__ void load_row(const float* __restrict__ o,
                                         const float* __restrict__ n,
                                         int off, int x0, int xl, int xr,
                                         float avg[4], float& l, float& r,
                                         float dt[4])
{
    float4 ov = *(const float4*)(o + off + x0);
    float4 nv = *(const float4*)(n + off + x0);
    avg[0] = 0.5f*(ov.x+nv.x); avg[1] = 0.5f*(ov.y+nv.y);
    avg[2] = 0.5f*(ov.z+nv.z); avg[3] = 0.5f*(ov.w+nv.w);
    dt[0] = (nv.x-ov.x)*INV_DT; dt[1] = (nv.y-ov.y)*INV_DT;
    dt[2] = (nv.z-ov.z)*INV_DT; dt[3] = (nv.w-ov.w)*INV_DT;
    // clamped halos: only ever consumed for interior pixels, clamp keeps
    // row-0 / row-(H-1) loads inside the allocation.
    l = 0.5f*(o[off + xl] + n[off + xl]);
    r = 0.5f*(o[off + xr] + n[off + xr]);
}

__global__ __launch_bounds__(256) void ns_loss_kernel(
    const float* __restrict__ v_old,
    const float* __restrict__ v_new,
    const float* __restrict__ p_new,
    const int*   __restrict__ mask)
{
    const int b    = blockIdx.z;
    const int y0   = 1 + blockIdx.y * ROWS;          // first center row
    const int yend = min(y0 + ROWS, H - 1);          // exclusive
    const int x0   = threadIdx.x * 4;
    const int xl   = (x0 > 0) ? x0 - 1 : 0;
    const int xr   = (x0 + 4 < W) ? x0 + 4 : W - 1;

    const size_t plane = (size_t)H * W;
    const float* uo = v_old + (size_t)b * 2 * plane;      // channel 0 = u
    const float* wo = uo + plane;                          // channel 1 = w
    const float* un = v_new + (size_t)b * 2 * plane;
    const float* wn = un + plane;
    const float* pp = p_new + (size_t)b * plane;
    const int*   mm = mask  + (size_t)b * plane;

    // rolling state: [0]=y-1, [1]=y, [2]=y+1 (avg); halos/dt: [0]=cur,[1]=next
    float uA[3][4], wA[3][4];
    float uL[2], uR[2], wL[2], wR[2];
    float du[2][4], dw[2][4];
    float pPrev[4], pCur[4], pL;

    // ---- prologue: rows y0-1 and y0 ----
    {
        float tl, tr, tdt[4];
        load_row(uo, un, (y0-1)*W, x0, xl, xr, uA[0], tl, tr, tdt);
        load_row(wo, wn, (y0-1)*W, x0, xl, xr, wA[0], tl, tr, tdt);
    }
    load_row(uo, un, y0*W, x0, xl, xr, uA[1], uL[0], uR[0], du[0]);
    load_row(wo, wn, y0*W, x0, xl, xr, wA[1], wL[0], wR[0], dw[0]);
    {
        float4 pm = *(const float4*)(pp + (y0-1)*W + x0);
        pPrev[0]=pm.x; pPrev[1]=pm.y; pPrev[2]=pm.z; pPrev[3]=pm.w;
        float4 pc = *(const float4*)(pp + y0*W + x0);
        pCur[0]=pc.x; pCur[1]=pc.y; pCur[2]=pc.z; pCur[3]=pc.w;
        pL = pp[y0*W + x0 - 1];   // x0=0 -> row y0-1 col W-1: in-bounds, value unused
    }

    float local = 0.0f;

    for (int y = y0; y < yend; ++y) {
        // ---- load row y+1 (becomes yp for this iteration) ----
        const int offp = (y + 1) * W;
        load_row(uo, un, offp, x0, xl, xr, uA[2], uL[1], uR[1], du[1]);
        load_row(wo, wn, offp, x0, xl, xr, wA[2], wL[1], wR[1], dw[1]);
        float4 pn4 = *(const float4*)(pp + offp + x0);
        float  pLn = pp[offp + x0 - 1];
        int4   mk  = *(const int4*)(mm + y*W + x0);

        // ---- compute residuals at center row y ----
        const float uc6[6] = {uL[0], uA[1][0], uA[1][1], uA[1][2], uA[1][3], uR[0]};
        const float wc6[6] = {wL[0], wA[1][0], wA[1][1], wA[1][2], wA[1][3], wR[0]};
        const float pc5[5] = {pL, pCur[0], pCur[1], pCur[2], pCur[3]};
        const int   mk4[4] = {mk.x, mk.y, mk.z, mk.w};

        #pragma unroll
        for (int j = 0; j < 4; ++j) {
            const float u_c  = uc6[j+1], u_xm = uc6[j], u_xp = uc6[j+2];
            const float w_c  = wc6[j+1], w_xm = wc6[j], w_xp = wc6[j+2];
            const float u_ym = uA[0][j], u_yp = uA[2][j];
            const float w_ym = wA[0][j], w_yp = wA[2][j];

            // res_x (RHO = 1)
            float rx = dw[0][j]
                     + w_c * 0.5f * (w_xp - w_xm)
                     + 0.5f * ( 0.5f*(u_c + u_xm) * (w_c - w_ym)
                              + 0.5f*(u_c + u_xp) * (w_yp - w_c) )
                     + (pc5[j+1] - pc5[j])
                     - MU * (w_xm + w_xp + w_ym + w_yp - 4.0f * w_c);

            // res_y
            float ry = du[0][j]
                     + u_c * 0.5f * (u_yp - u_ym)
                     + 0.5f * ( 0.5f*(w_c + w_ym) * (u_c - u_xm)
                              + 0.5f*(w_c + w_yp) * (u_xp - u_c) )
                     + (pc5[j+1] - pPrev[j])
                     - MU * (u_xm + u_xp + u_ym + u_yp - 4.0f * u_c);

            const float mf = (float)mk4[j];
            rx *= mf;
            ry *= mf;

            const int x = x0 + j;
            if (x >= 1 && x <= W - 2)
                local += rx * rx + ry * ry;
        }

        // ---- rotate rolling state ----
        #pragma unroll
        for (int k = 0; k < 4; ++k) {
            uA[0][k] = uA[1][k]; uA[1][k] = uA[2][k];
            wA[0][k] = wA[1][k]; wA[1][k] = wA[2][k];
            du[0][k] = du[1][k]; dw[0][k] = dw[1][k];
            pPrev[k] = pCur[k];
        }
        uL[0] = uL[1]; uR[0] = uR[1]; wL[0] = wL[1]; wR[0] = wR[1];
        pCur[0] = pn4.x; pCur[1] = pn4.y; pCur[2] = pn4.z; pCur[3] = pn4.w;
        pL = pLn;
    }

    // ---- block reduction ----
    #pragma unroll
    for (int o = 16; o > 0; o >>= 1)
        local += __shfl_xor_sync(0xffffffffu, local, o);

    __shared__ float s_part[8];
    const int lane = threadIdx.x & 31;
    const int wid  = threadIdx.x >> 5;
    if (lane == 0) s_part[wid] = local;
    __syncthreads();
    if (wid == 0) {
        float v = (lane < 8) ? s_part[lane] : 0.0f;
        #pragma unroll
        for (int o = 4; o > 0; o >>= 1)
            v += __shfl_xor_sync(0xffffffffu, v, o);
        if (lane == 0)
            atomicAdd(&g_accum[b], (double)v);
    }
}

__global__ void ns_fin_kernel(float* __restrict__ out) {
    if (threadIdx.x < B) {
        const double inv_cnt = 1.0 / ((double)(H - 2) * (double)(W - 2));
        out[threadIdx.x] = (float)(g_accum[threadIdx.x] * inv_cnt);
    }
}

extern "C" void kernel_launch(void* const* d_in, const int* in_sizes, int n_in,
                              void* d_out, int out_size) {
    const float* v_old = (const float*)d_in[0];
    const float* v_new = (const float*)d_in[1];
    const float* p_new = (const float*)d_in[2];
    const int*   mask  = (const int*)d_in[3];
    float* out = (float*)d_out;

    ns_zero_kernel<<<1, 32>>>();
    dim3 grid(1, (H - 2 + ROWS - 1) / ROWS, B);   // 128 x 8 = 1024 blocks
    ns_loss_kernel<<<grid, 256>>>(v_old, v_new, p_new, mask);
    ns_fin_kernel<<<1, 32>>>(out);
}